// round 13
// baseline (speedup 1.0000x reference)
#include <cuda_runtime.h>
#include <cuda_bf16.h>
#include <math.h>
#include <cstdint>

#define NN 1500
#define NE 1200
#define NB 96
#define NSEG 1536
#define K2 3072            // storage K width: 2 segments [h | l]
#define NTOT 3072          // output rows (interleaved: 2n=mu(n), 2n+1=s2(n))
#define MM 96              // batch rows (6 x m16)
#define NT 128             // N-tile per CTA
#define NTILES 24          // NTOT/NT
#define KSP 12             // split-K over the real axis
#define KR 128             // real-k per CTA = NSEG/KSP
#define KCH 32             // real-k per smem chunk
#define CH 4               // KR/KCH
#define NSTEPS 60
#define UTOT (NB * NN)
#define NCTA (NTILES * KSP)          // 288
#define UPC 500                      // update items per CTA = UTOT/NCTA

// padded smem row: 32 bf16 data + 8 pad = 40 bf16 = 80 bytes (ldmatrix conflict-free)
#define ROWB 80
#define T_A (MM * ROWB)              // 7680
#define T_B (NT * ROWB)              // 10240
#define OFF_AH 0
#define OFF_AL T_A
#define OFF_BH (2 * T_A)
#define OFF_BL (2 * T_A + T_B)
#define BUFSZ (2 * T_A + 2 * T_B)    // 35840
#define SMEM_TOTAL (3 * BUFSZ)       // 107520 (triple buffer)

typedef unsigned int u32;
typedef unsigned long long u64;

// ---------------- static device buffers ----------------
__device__ __align__(16) __nv_bfloat16 d_A[(size_t)MM * K2];       // [b][ah|al]
__device__ __align__(16) __nv_bfloat16 d_B[(size_t)NTOT * K2];     // [r][h|l] 18.9MB
__device__ __align__(16) float d_part[(size_t)KSP * NB * NTOT];    // 14.2MB
__device__ __align__(16) float d_rate[NB * NN];
__device__ __align__(16) float d_mean[NB * NN];
__device__ u32 d_cnt_arr = 0;
__device__ u32 d_cnt_dep = 0;

__constant__ float c_contr[8] = {0.0f, 0.0432773f, 0.103411f, 0.186966f,
                                 0.303066f, 0.464386f, 0.68854f, 1.0f};

// ---------------- PTX helpers (base ISA only) ----------------
__device__ __forceinline__ u32 smem_u32(const void* p) {
    u32 a;
    asm("{ .reg .u64 t; cvta.to.shared.u64 t, %1; cvt.u32.u64 %0, t; }" : "=r"(a) : "l"(p));
    return a;
}
__device__ __forceinline__ void ldsm4(u32& r0, u32& r1, u32& r2, u32& r3, u32 addr) {
    asm volatile("ldmatrix.sync.aligned.m8n8.x4.shared.b16 {%0,%1,%2,%3}, [%4];"
                 : "=r"(r0), "=r"(r1), "=r"(r2), "=r"(r3) : "r"(addr));
}
__device__ __forceinline__ void cpasync16(u32 saddr, const void* gaddr) {
    asm volatile("cp.async.cg.shared.global [%0], [%1], 16;" :: "r"(saddr), "l"(gaddr));
}
__device__ __forceinline__ void mma16816(float* c, u32 a0, u32 a1, u32 a2, u32 a3,
                                         u32 b0, u32 b1) {
    asm volatile("mma.sync.aligned.m16n8k16.row.col.f32.bf16.bf16.f32 "
                 "{%0,%1,%2,%3}, {%4,%5,%6,%7}, {%8,%9}, {%0,%1,%2,%3};"
                 : "+f"(c[0]), "+f"(c[1]), "+f"(c[2]), "+f"(c[3])
                 : "r"(a0), "r"(a1), "r"(a2), "r"(a3), "r"(b0), "r"(b1));
}

// ---------------- math helpers ----------------
__device__ __forceinline__ float prefv(int n) {
    const float se = 179.99f / 1200.0f;
    const float si = 179.99f / 300.0f;
    return (n < NE) ? (float)n * se : (float)(n - NE) * si;
}
__device__ __forceinline__ float f_ricci(float x) {
    float z = x / (1.0f + x);
    float t = -z;
    float p = 0.14805913578876898f;
    p = p * t + 0.64290613877355551f;
    p = p * t + 1.0616084849547165f;
    p = p * t + 0.93524391761244940f;
    p = p * t + 0.62718906618071668f;
    p = p * t + 0.32171431660633076f;
    p = p * t + 0.32056016125642045f;
    p = p * t + 0.77373949685442023f;
    p = p * t + 0.22757881388024176f;
    p = p * t + 0.0f;
    return logf(2.0f * x + 1.0f) + p;
}
__device__ __forceinline__ float g_ricci(float x) {
    float z = x / (2.0f + x);
    float num = z * (3.5441754117462949f + z * (-7.0529131065835378f + z * (-56.532378057580381f
              + z * (279.56761105465944f + z * (-520.37554849441472f + z * (456.58245777026514f
              + z * (-155.73340457809226f)))))));
    float den = 1.0f + z * (-4.1357968834226053f + z * (-7.2984226138266743f + z * (98.656602235468327f
              + z * (-334.20436223415163f + z * (601.08633903294185f + z * (-599.58577549598340f
              + z * (277.18420330693891f + z * (-16.445022798669722f))))))));
    return num / den;
}
__device__ __forceinline__ float phi_f(float mu, float sig, float tau_ref) {
    const float tau = 0.01f;
    float xp = mu / sig;
    float xm = (mu - 20.0f) / sig;
    float r0;
    if (xm > 0.0f) {
        r0 = 1.0f / (f_ricci(xp) - f_ricci(xm));
    } else if (xp > 0.0f) {
        r0 = 1.0f / (f_ricci(xp) + expf(xm * xm) * g_ricci(-xm));
    } else {
        r0 = expf(-xm * xm - logf(g_ricci(-xm) - expf(xp * xp - xm * xm) * g_ricci(-xp)));
    }
    r0 = fmaxf(r0, 1e-30f);
    return 1.0f / (tau_ref + tau / r0);
}

// shared update math (R12-validated)
__device__ __forceinline__ void do_update(int item, int first, int last, float* out) {
    int b = item / NN;
    int n = item - b * NN;
    float ms = 0.0f, ss = 0.0f, rold = 0.0f;
    if (!first) {
        rold = d_rate[item];
        const float* pp = d_part + (size_t)b * NTOT + 2 * n;
#pragma unroll
        for (int z = 0; z < KSP; z++) {
            float2 v = *(const float2*)(pp + (size_t)z * NB * NTOT);
            ms += v.x; ss += v.y;
        }
    }
    float mu  = 0.01f * ms + d_mean[item];
    float sig = sqrtf(0.01f * ss + 25.0f);
    float tr = (n < NE) ? 0.005f : 0.001f;
    float aT = (n < NE) ? 0.1f : 0.2f;
    float ph = phi_f(mu, sig, tr);
    float rnew = rold + aT * (ph - rold);
    d_rate[item] = rnew;
    __nv_bfloat16 ah = __float2bfloat16(rnew);
    __nv_bfloat16 al = __float2bfloat16(rnew - __bfloat162float(ah));
    size_t ar = (size_t)b * K2 + n;
    d_A[ar]        = ah;
    d_A[ar + NSEG] = al;
    if (last) out[(size_t)n * NB + b] = rnew;        // out[n][b] = rate[b][n]
}

// ---------------- setup kernels ----------------
__global__ void k_weightsB(const float* __restrict__ hyp, const float* __restrict__ rnd) {
    int tid = blockIdx.x * blockDim.x + threadIdx.x;
    if (tid >= NSEG * NSEG) return;
    int i = tid / NSEG;
    int j = tid - i * NSEG;
    float w = 0.0f;
    if (i < NN && j < NN) {
        int conn = (i >= NE ? 1 : 0) + 2 * (j >= NE ? 1 : 0);
        float J = hyp[conn], P = hyp[4 + conn], Wp = hyp[8 + conn];
        const float cd = 3.14159265358979323846f / 180.0f;
        float diff = fabsf(prefv(i) - prefv(j));
        float wden = 4.0f * (cd * Wp) * (cd * Wp);
        float z = expf((cosf(2.0f * cd * diff) - 1.0f) / wden);
        float x = 32.0f * (P * z - rnd[(size_t)i * NN + j]);
        w = J / (1.0f + expf(-x));
    }
    float w2 = w * w;
    __nv_bfloat16 wh = __float2bfloat16(w);
    __nv_bfloat16 wl = __float2bfloat16(w - __bfloat162float(wh));
    __nv_bfloat16 vh = __float2bfloat16(w2);
    __nv_bfloat16 vl = __float2bfloat16(w2 - __bfloat162float(vh));
    size_t r1 = (size_t)(2 * i) * K2;
    size_t r2 = (size_t)(2 * i + 1) * K2;
    d_B[r1 + j] = wh; d_B[r1 + NSEG + j] = wl;
    d_B[r2 + j] = vh; d_B[r2 + NSEG + j] = vl;
}

__global__ void k_mean() {
    int tid = blockIdx.x * blockDim.x + threadIdx.x;
    if (tid >= NB * NN) return;
    int b = tid / NN;
    int n = tid - b * NN;
    int c = b / 12;
    int o = b - c * 12;
    const float cd = 3.14159265358979323846f / 180.0f;
    float dth = (float)o * 15.0f - prefv(n);
    const float wden = 4.0f * (cd * 30.0f) * (cd * 30.0f);
    float cg = expf((cosf(2.0f * cd * dth) - 1.0f) / wden);
    d_mean[tid] = c_contr[c] * 20.0f * cg;
}

__global__ void k_zeroA() {
    int tid = blockIdx.x * blockDim.x + threadIdx.x;
    if (tid < MM * K2) d_A[tid] = __float2bfloat16(0.0f);
}

// ---------------- GEMM phase (shared by fused and fallback kernels) ----------------
__device__ __forceinline__ void mma_phase(char* sm) {
    u32 sb = smem_u32(sm);
    const int tid = threadIdx.x, wid = tid >> 5, lane = tid & 31;
    const int n0 = blockIdx.x * NT;
    const int z = blockIdx.y;
    const int kbase = z * KR;

    const char* Agc = (const char*)d_A;
    const char* Bgc = (const char*)d_B;

    float acc[3][4][4];
#pragma unroll
    for (int mt = 0; mt < 3; mt++)
#pragma unroll
        for (int j = 0; j < 4; j++)
#pragma unroll
            for (int q = 0; q < 4; q++) acc[mt][j][q] = 0.0f;

    const int m_w = (wid & 1) * 48;
    const int n_off = (wid >> 1) * 32;
    const int aRow = m_w + ((lane >> 3) & 1) * 8 + (lane & 7);
    const u32 aOff = (u32)(aRow * ROWB + ((lane >> 4) & 1) * 16);
    const int bRow = n_off + ((lane >> 4) & 1) * 8 + (lane & 7);
    const u32 bOff = (u32)(bRow * ROWB + ((lane >> 3) & 1) * 16);

    auto load_chunk = [&](int c, u32 buf) {
        int kg = kbase + c * KCH;
#pragma unroll
        for (int idx = tid; idx < MM * 4; idx += 256) {
            int row = idx >> 2, q = idx & 3;
            u32 so = (u32)(row * ROWB + q * 16);
            size_t go = ((size_t)row * K2 + kg + q * 8) * 2;
            cpasync16(buf + OFF_AH + so, Agc + go);
            cpasync16(buf + OFF_AL + so, Agc + go + (size_t)NSEG * 2);
        }
#pragma unroll
        for (int idx = tid; idx < NT * 4; idx += 256) {
            int row = idx >> 2, q = idx & 3;
            u32 so = (u32)(row * ROWB + q * 16);
            size_t go = ((size_t)(n0 + row) * K2 + kg + q * 8) * 2;
            cpasync16(buf + OFF_BH + so, Bgc + go);
            cpasync16(buf + OFF_BL + so, Bgc + go + (size_t)NSEG * 2);
        }
        asm volatile("cp.async.commit_group;" ::: "memory");
    };

    load_chunk(0, sb);
    load_chunk(1, sb + BUFSZ);

#pragma unroll
    for (int c = 0; c < CH; c++) {
        if (c < CH - 1) {
            asm volatile("cp.async.wait_group 1;" ::: "memory");
        } else {
            asm volatile("cp.async.wait_group 0;" ::: "memory");
        }
        __syncthreads();
        if (c + 2 < CH) load_chunk(c + 2, sb + ((c + 2) % 3) * (u32)BUFSZ);

        u32 buf = sb + (c % 3) * (u32)BUFSZ;
#pragma unroll
        for (int ks = 0; ks < 2; ks++) {
            u32 kcol = (u32)(ks * 32);
            u32 ah[3][4], al[3][4];
#pragma unroll
            for (int mt = 0; mt < 3; mt++) {
                u32 off = aOff + (u32)(mt * 16 * ROWB) + kcol;
                ldsm4(ah[mt][0], ah[mt][1], ah[mt][2], ah[mt][3], buf + OFF_AH + off);
                ldsm4(al[mt][0], al[mt][1], al[mt][2], al[mt][3], buf + OFF_AL + off);
            }
#pragma unroll
            for (int jp = 0; jp < 2; jp++) {
                u32 off = bOff + (u32)(jp * 16 * ROWB) + kcol;
                u32 h00, h01, h10, h11, l00, l01, l10, l11;
                ldsm4(h00, h01, h10, h11, buf + OFF_BH + off);
                ldsm4(l00, l01, l10, l11, buf + OFF_BL + off);
#pragma unroll
                for (int mt = 0; mt < 3; mt++) {
                    mma16816(acc[mt][2 * jp],     ah[mt][0], ah[mt][1], ah[mt][2], ah[mt][3], h00, h01);
                    mma16816(acc[mt][2 * jp + 1], ah[mt][0], ah[mt][1], ah[mt][2], ah[mt][3], h10, h11);
                    mma16816(acc[mt][2 * jp],     ah[mt][0], ah[mt][1], ah[mt][2], ah[mt][3], l00, l01);
                    mma16816(acc[mt][2 * jp + 1], ah[mt][0], ah[mt][1], ah[mt][2], ah[mt][3], l10, l11);
                    mma16816(acc[mt][2 * jp],     al[mt][0], al[mt][1], al[mt][2], al[mt][3], h00, h01);
                    mma16816(acc[mt][2 * jp + 1], al[mt][0], al[mt][1], al[mt][2], al[mt][3], h10, h11);
                }
            }
        }
    }

    const int grp = lane >> 2;
#pragma unroll
    for (int mt = 0; mt < 3; mt++) {
        int br0 = m_w + mt * 16 + grp;
        int br1 = br0 + 8;
#pragma unroll
        for (int j = 0; j < 4; j++) {
            int col = n0 + n_off + j * 8 + (lane & 3) * 2;
            *(float2*)(d_part + ((size_t)z * NB + br0) * NTOT + col) =
                make_float2(acc[mt][j][0], acc[mt][j][1]);
            *(float2*)(d_part + ((size_t)z * NB + br1) * NTOT + col) =
                make_float2(acc[mt][j][2], acc[mt][j][3]);
        }
    }
}

// ---------------- fused step: mma + grid barrier + update ----------------
__global__ __launch_bounds__(256, 2) void k_step(int last, float* __restrict__ out) {
    extern __shared__ char sm[];
    mma_phase(sm);

    // publish partials, then grid-wide arrive
    __threadfence();
    __syncthreads();
    if (threadIdx.x == 0) {
        atomicAdd(&d_cnt_arr, 1u);
        while (atomicAdd(&d_cnt_arr, 0u) < (u32)NCTA) __nanosleep(64);
    }
    __syncthreads();
    __threadfence();

    // update phase: this CTA's 500 items
    int cta = blockIdx.y * NTILES + blockIdx.x;      // 0..287
    int base = cta * UPC;
#pragma unroll
    for (int t = (int)threadIdx.x; t < UPC; t += 256)
        do_update(base + t, 0, last, out);

    // depart; last CTA resets both counters (everyone has passed the spin)
    if (threadIdx.x == 0) {
        u32 d = atomicAdd(&d_cnt_dep, 1u);
        if (d == (u32)(NCTA - 1)) {
            atomicExch(&d_cnt_arr, 0u);
            atomicExch(&d_cnt_dep, 0u);
        }
    }
}

// ---------------- fallback path kernels (validated R12) ----------------
__global__ __launch_bounds__(256, 2) void k_mma() {
    extern __shared__ char sm[];
    mma_phase(sm);
}
__global__ void k_update(int first, int last, float* __restrict__ out) {
    int tid = blockIdx.x * blockDim.x + threadIdx.x;
    if (tid >= UTOT) return;
    do_update(tid, first, last, out);
}

// ---------------- launch ----------------
extern "C" void kernel_launch(void* const* d_in, const int* in_sizes, int n_in,
                              void* d_out, int out_size) {
    const float* hyp = (const float*)d_in[0];
    const float* rnd = (const float*)d_in[1];
    float* out = (float*)d_out;

    cudaFuncSetAttribute(k_mma, cudaFuncAttributeMaxDynamicSharedMemorySize, SMEM_TOTAL);
    cudaFuncSetAttribute(k_step, cudaFuncAttributeMaxDynamicSharedMemorySize, SMEM_TOTAL);

    // co-residency check for the in-kernel grid barrier (deadlock safety)
    int perSM = 0, nSM = 0, dev = 0;
    cudaGetDevice(&dev);
    cudaDeviceGetAttribute(&nSM, cudaDevAttrMultiProcessorCount, dev);
    cudaOccupancyMaxActiveBlocksPerMultiprocessor(&perSM, k_step, 256, SMEM_TOTAL);
    bool fused = (perSM * nSM >= NCTA);

    k_weightsB<<<(NSEG * NSEG + 255) / 256, 256>>>(hyp, rnd);
    k_mean<<<(NB * NN + 255) / 256, 256>>>();
    k_zeroA<<<(MM * K2 + 255) / 256, 256>>>();

    const int UB = (UTOT + 255) / 256;
    k_update<<<UB, 256>>>(1, 0, out);                 // step 1: rate=0 -> mu=mean
    if (fused) {
        for (int s = 1; s < NSTEPS; s++)
            k_step<<<dim3(NTILES, KSP), 256, SMEM_TOTAL>>>(s == NSTEPS - 1 ? 1 : 0, out);
    } else {
        for (int s = 1; s < NSTEPS; s++) {
            k_mma<<<dim3(NTILES, KSP), 256, SMEM_TOTAL>>>();
            k_update<<<UB, 256>>>(0, s == NSTEPS - 1 ? 1 : 0, out);
        }
    }
}

// round 14
// speedup vs baseline: 1.1279x; 1.1279x over previous
#include <cuda_runtime.h>
#include <cuda_bf16.h>
#include <math.h>
#include <cstdint>

#define NN 1500
#define NE 1200
#define NB 96
#define NSEG 1536
#define K2 3072            // storage K width: 2 segments [h | l]
#define NTOT 3072          // output rows (interleaved: 2n=mu(n), 2n+1=s2(n))
#define MM 96              // batch rows (6 x m16)
#define NT 128             // N-tile per CTA
#define NTILES 24          // NTOT/NT
#define KSP 12             // split-K over the real axis
#define KR 128             // real-k per CTA = NSEG/KSP
#define KCH 32             // real-k per smem chunk
#define CH 4               // KR/KCH
#define NSTEPS 60
#define UTOT (NB * NN)

// padded smem row: 32 bf16 data + 8 pad = 40 bf16 = 80 bytes (ldmatrix conflict-free)
#define ROWB 80
#define T_A (MM * ROWB)              // 7680
#define T_B (NT * ROWB)              // 10240
#define OFF_AH 0
#define OFF_AL T_A
#define OFF_BH (2 * T_A)
#define OFF_BL (2 * T_A + T_B)
#define BUFSZ (2 * T_A + 2 * T_B)    // 35840
#define SMEM_TOTAL (3 * BUFSZ)       // 107520 (triple buffer)

typedef unsigned int u32;
typedef unsigned long long u64;

// ---------------- static device buffers ----------------
__device__ __align__(16) __nv_bfloat16 d_A[(size_t)MM * K2];       // [b][ah|al]
__device__ __align__(16) __nv_bfloat16 d_B[(size_t)NTOT * K2];     // [r][h|l] 18.9MB
__device__ __align__(16) float d_part[(size_t)KSP * NB * NTOT];    // 14.2MB
__device__ __align__(16) float d_rate[NB * NN];
__device__ __align__(16) float d_mean[NB * NN];

__constant__ float c_contr[8] = {0.0f, 0.0432773f, 0.103411f, 0.186966f,
                                 0.303066f, 0.464386f, 0.68854f, 1.0f};

// ---------------- PTX helpers (base ISA only) ----------------
__device__ __forceinline__ u32 smem_u32(const void* p) {
    u32 a;
    asm("{ .reg .u64 t; cvta.to.shared.u64 t, %1; cvt.u32.u64 %0, t; }" : "=r"(a) : "l"(p));
    return a;
}
__device__ __forceinline__ void ldsm4(u32& r0, u32& r1, u32& r2, u32& r3, u32 addr) {
    asm volatile("ldmatrix.sync.aligned.m8n8.x4.shared.b16 {%0,%1,%2,%3}, [%4];"
                 : "=r"(r0), "=r"(r1), "=r"(r2), "=r"(r3) : "r"(addr));
}
__device__ __forceinline__ void cpasync16(u32 saddr, const void* gaddr) {
    asm volatile("cp.async.cg.shared.global [%0], [%1], 16;" :: "r"(saddr), "l"(gaddr));
}
__device__ __forceinline__ void mma16816(float* c, u32 a0, u32 a1, u32 a2, u32 a3,
                                         u32 b0, u32 b1) {
    asm volatile("mma.sync.aligned.m16n8k16.row.col.f32.bf16.bf16.f32 "
                 "{%0,%1,%2,%3}, {%4,%5,%6,%7}, {%8,%9}, {%0,%1,%2,%3};"
                 : "+f"(c[0]), "+f"(c[1]), "+f"(c[2]), "+f"(c[3])
                 : "r"(a0), "r"(a1), "r"(a2), "r"(a3), "r"(b0), "r"(b1));
}

// ---------------- math helpers (MUFU fast-math; rel err ~1e-6 << 1e-3 budget) ----
__device__ __forceinline__ float prefv(int n) {
    const float se = 179.99f / 1200.0f;
    const float si = 179.99f / 300.0f;
    return (n < NE) ? (float)n * se : (float)(n - NE) * si;
}
__device__ __forceinline__ float f_ricci(float x) {
    float z = x / (1.0f + x);
    float t = -z;
    float p = 0.14805913578876898f;
    p = p * t + 0.64290613877355551f;
    p = p * t + 1.0616084849547165f;
    p = p * t + 0.93524391761244940f;
    p = p * t + 0.62718906618071668f;
    p = p * t + 0.32171431660633076f;
    p = p * t + 0.32056016125642045f;
    p = p * t + 0.77373949685442023f;
    p = p * t + 0.22757881388024176f;
    p = p * t + 0.0f;
    return __logf(2.0f * x + 1.0f) + p;
}
__device__ __forceinline__ float g_ricci(float x) {
    float z = x / (2.0f + x);
    float num = z * (3.5441754117462949f + z * (-7.0529131065835378f + z * (-56.532378057580381f
              + z * (279.56761105465944f + z * (-520.37554849441472f + z * (456.58245777026514f
              + z * (-155.73340457809226f)))))));
    float den = 1.0f + z * (-4.1357968834226053f + z * (-7.2984226138266743f + z * (98.656602235468327f
              + z * (-334.20436223415163f + z * (601.08633903294185f + z * (-599.58577549598340f
              + z * (277.18420330693891f + z * (-16.445022798669722f))))))));
    return num / den;
}
__device__ __forceinline__ float phi_f(float mu, float sig, float tau_ref) {
    const float tau = 0.01f;
    float xp = mu / sig;
    float xm = (mu - 20.0f) / sig;
    float r0;
    if (xm > 0.0f) {
        r0 = 1.0f / (f_ricci(xp) - f_ricci(xm));
    } else if (xp > 0.0f) {
        r0 = 1.0f / (f_ricci(xp) + __expf(xm * xm) * g_ricci(-xm));
    } else {
        r0 = __expf(-xm * xm - __logf(g_ricci(-xm) - __expf(xp * xp - xm * xm) * g_ricci(-xp)));
    }
    r0 = fmaxf(r0, 1e-30f);
    return 1.0f / (tau_ref + tau / r0);
}

// ---------------- setup kernels ----------------
// B row 2i   (mu neuron i): segments [wh  | wl ]
// B row 2i+1 (s2 neuron i): segments [w2h | w2l]
// A segments [ah | al]; step computes ah*wh + ah*wl + al*wh (error ~2^-18)
__global__ void k_weightsB(const float* __restrict__ hyp, const float* __restrict__ rnd) {
    int tid = blockIdx.x * blockDim.x + threadIdx.x;
    if (tid >= NSEG * NSEG) return;
    int i = tid / NSEG;          // output neuron
    int j = tid - i * NSEG;      // input neuron (K)
    float w = 0.0f;
    if (i < NN && j < NN) {
        int conn = (i >= NE ? 1 : 0) + 2 * (j >= NE ? 1 : 0);
        float J = hyp[conn], P = hyp[4 + conn], Wp = hyp[8 + conn];
        const float cd = 3.14159265358979323846f / 180.0f;
        float diff = fabsf(prefv(i) - prefv(j));
        float wden = 4.0f * (cd * Wp) * (cd * Wp);
        float z = __expf((__cosf(2.0f * cd * diff) - 1.0f) / wden);
        float x = 32.0f * (P * z - rnd[(size_t)i * NN + j]);
        w = J / (1.0f + __expf(-x));
    }
    float w2 = w * w;
    __nv_bfloat16 wh = __float2bfloat16(w);
    __nv_bfloat16 wl = __float2bfloat16(w - __bfloat162float(wh));
    __nv_bfloat16 vh = __float2bfloat16(w2);
    __nv_bfloat16 vl = __float2bfloat16(w2 - __bfloat162float(vh));
    size_t r1 = (size_t)(2 * i) * K2;
    size_t r2 = (size_t)(2 * i + 1) * K2;
    d_B[r1 + j] = wh; d_B[r1 + NSEG + j] = wl;
    d_B[r2 + j] = vh; d_B[r2 + NSEG + j] = vl;
}

__global__ void k_mean() {
    int tid = blockIdx.x * blockDim.x + threadIdx.x;
    if (tid >= NB * NN) return;
    int b = tid / NN;
    int n = tid - b * NN;
    int c = b / 12;
    int o = b - c * 12;
    const float cd = 3.14159265358979323846f / 180.0f;
    float dth = (float)o * 15.0f - prefv(n);
    const float wden = 4.0f * (cd * 30.0f) * (cd * 30.0f);
    float cg = __expf((__cosf(2.0f * cd * dth) - 1.0f) / wden);
    d_mean[tid] = c_contr[c] * 20.0f * cg;
}

__global__ void k_zeroA() {
    int tid = blockIdx.x * blockDim.x + threadIdx.x;
    if (tid < MM * K2) d_A[tid] = __float2bfloat16(0.0f);
}

// ---------------- bf16 mma.sync GEMM step (R12-validated) ----------------
// grid (24 n-tiles, 12 split-K), 256 threads.
// Per chunk (32 real-k): smem tiles Ah, Al, Bh, Bl; three MMA pairings reuse them:
//   acc += Ah*Bh + Ah*Bl + Al*Bh
// Triple-buffered cp.async pipeline (distance 2, one barrier/chunk).
__global__ __launch_bounds__(256, 2) void k_mma() {
    extern __shared__ char sm[];
    u32 sb = smem_u32(sm);
    const int tid = threadIdx.x, wid = tid >> 5, lane = tid & 31;
    const int n0 = blockIdx.x * NT;
    const int z = blockIdx.y;
    const int kbase = z * KR;

    const char* Agc = (const char*)d_A;
    const char* Bgc = (const char*)d_B;

    float acc[3][4][4];
#pragma unroll
    for (int mt = 0; mt < 3; mt++)
#pragma unroll
        for (int j = 0; j < 4; j++)
#pragma unroll
            for (int q = 0; q < 4; q++) acc[mt][j][q] = 0.0f;

    const int m_w = (wid & 1) * 48;
    const int n_off = (wid >> 1) * 32;
    const int aRow = m_w + ((lane >> 3) & 1) * 8 + (lane & 7);
    const u32 aOff = (u32)(aRow * ROWB + ((lane >> 4) & 1) * 16);
    const int bRow = n_off + ((lane >> 4) & 1) * 8 + (lane & 7);
    const u32 bOff = (u32)(bRow * ROWB + ((lane >> 3) & 1) * 16);

    auto load_chunk = [&](int c, u32 buf) {
        int kg = kbase + c * KCH;
#pragma unroll
        for (int idx = tid; idx < MM * 4; idx += 256) {
            int row = idx >> 2, q = idx & 3;
            u32 so = (u32)(row * ROWB + q * 16);
            size_t go = ((size_t)row * K2 + kg + q * 8) * 2;
            cpasync16(buf + OFF_AH + so, Agc + go);
            cpasync16(buf + OFF_AL + so, Agc + go + (size_t)NSEG * 2);
        }
#pragma unroll
        for (int idx = tid; idx < NT * 4; idx += 256) {
            int row = idx >> 2, q = idx & 3;
            u32 so = (u32)(row * ROWB + q * 16);
            size_t go = ((size_t)(n0 + row) * K2 + kg + q * 8) * 2;
            cpasync16(buf + OFF_BH + so, Bgc + go);
            cpasync16(buf + OFF_BL + so, Bgc + go + (size_t)NSEG * 2);
        }
        asm volatile("cp.async.commit_group;" ::: "memory");
    };

    load_chunk(0, sb);
    load_chunk(1, sb + BUFSZ);

#pragma unroll
    for (int c = 0; c < CH; c++) {
        if (c < CH - 1) {
            asm volatile("cp.async.wait_group 1;" ::: "memory");
        } else {
            asm volatile("cp.async.wait_group 0;" ::: "memory");
        }
        __syncthreads();
        if (c + 2 < CH) load_chunk(c + 2, sb + ((c + 2) % 3) * (u32)BUFSZ);

        u32 buf = sb + (c % 3) * (u32)BUFSZ;
#pragma unroll
        for (int ks = 0; ks < 2; ks++) {
            u32 kcol = (u32)(ks * 32);
            u32 ah[3][4], al[3][4];
#pragma unroll
            for (int mt = 0; mt < 3; mt++) {
                u32 off = aOff + (u32)(mt * 16 * ROWB) + kcol;
                ldsm4(ah[mt][0], ah[mt][1], ah[mt][2], ah[mt][3], buf + OFF_AH + off);
                ldsm4(al[mt][0], al[mt][1], al[mt][2], al[mt][3], buf + OFF_AL + off);
            }
#pragma unroll
            for (int jp = 0; jp < 2; jp++) {
                u32 off = bOff + (u32)(jp * 16 * ROWB) + kcol;
                u32 h00, h01, h10, h11, l00, l01, l10, l11;
                ldsm4(h00, h01, h10, h11, buf + OFF_BH + off);
                ldsm4(l00, l01, l10, l11, buf + OFF_BL + off);
#pragma unroll
                for (int mt = 0; mt < 3; mt++) {
                    mma16816(acc[mt][2 * jp],     ah[mt][0], ah[mt][1], ah[mt][2], ah[mt][3], h00, h01);
                    mma16816(acc[mt][2 * jp + 1], ah[mt][0], ah[mt][1], ah[mt][2], ah[mt][3], h10, h11);
                    mma16816(acc[mt][2 * jp],     ah[mt][0], ah[mt][1], ah[mt][2], ah[mt][3], l00, l01);
                    mma16816(acc[mt][2 * jp + 1], ah[mt][0], ah[mt][1], ah[mt][2], ah[mt][3], l10, l11);
                    mma16816(acc[mt][2 * jp],     al[mt][0], al[mt][1], al[mt][2], al[mt][3], h00, h01);
                    mma16816(acc[mt][2 * jp + 1], al[mt][0], al[mt][1], al[mt][2], al[mt][3], h10, h11);
                }
            }
        }
    }

    const int grp = lane >> 2;
#pragma unroll
    for (int mt = 0; mt < 3; mt++) {
        int br0 = m_w + mt * 16 + grp;
        int br1 = br0 + 8;
#pragma unroll
        for (int j = 0; j < 4; j++) {
            int col = n0 + n_off + j * 8 + (lane & 3) * 2;
            *(float2*)(d_part + ((size_t)z * NB + br0) * NTOT + col) =
                make_float2(acc[mt][j][0], acc[mt][j][1]);
            *(float2*)(d_part + ((size_t)z * NB + br1) * NTOT + col) =
                make_float2(acc[mt][j][2], acc[mt][j][3]);
        }
    }
}

// ---------------- reduce + phi + Euler update + A split write ----------------
__global__ void k_update(int first, int last, float* __restrict__ out) {
    int tid = blockIdx.x * blockDim.x + threadIdx.x;
    if (tid >= UTOT) return;
    int b = tid / NN;
    int n = tid - b * NN;

    float ms = 0.0f, ss = 0.0f, rold = 0.0f;
    if (!first) {
        rold = d_rate[tid];
        const float* pp = d_part + (size_t)b * NTOT + 2 * n;
#pragma unroll
        for (int z = 0; z < KSP; z++) {
            float2 v = *(const float2*)(pp + (size_t)z * NB * NTOT);
            ms += v.x; ss += v.y;
        }
    }
    float mu  = 0.01f * ms + d_mean[tid];
    float sig = sqrtf(0.01f * ss + 25.0f);
    float tr = (n < NE) ? 0.005f : 0.001f;
    float aT = (n < NE) ? 0.1f : 0.2f;
    float ph = phi_f(mu, sig, tr);
    float rnew = rold + aT * (ph - rold);
    d_rate[tid] = rnew;

    __nv_bfloat16 ah = __float2bfloat16(rnew);
    __nv_bfloat16 al = __float2bfloat16(rnew - __bfloat162float(ah));
    size_t ar = (size_t)b * K2 + n;
    d_A[ar]        = ah;
    d_A[ar + NSEG] = al;

    if (last) out[(size_t)n * NB + b] = rnew;        // out[n][b] = rate[b][n]
}

// ---------------- launch ----------------
extern "C" void kernel_launch(void* const* d_in, const int* in_sizes, int n_in,
                              void* d_out, int out_size) {
    const float* hyp = (const float*)d_in[0];
    const float* rnd = (const float*)d_in[1];
    float* out = (float*)d_out;

    cudaFuncSetAttribute(k_mma, cudaFuncAttributeMaxDynamicSharedMemorySize, SMEM_TOTAL);

    k_weightsB<<<(NSEG * NSEG + 255) / 256, 256>>>(hyp, rnd);
    k_mean<<<(NB * NN + 255) / 256, 256>>>();
    k_zeroA<<<(MM * K2 + 255) / 256, 256>>>();

    const int UB = (UTOT + 255) / 256;
    k_update<<<UB, 256>>>(1, 0, out);                 // step 1: rate=0 -> mu=mean
    for (int s = 1; s < NSTEPS; s++) {
        k_mma<<<dim3(NTILES, KSP), 256, SMEM_TOTAL>>>();
        k_update<<<UB, 256>>>(0, s == NSTEPS - 1 ? 1 : 0, out);
    }
}

// round 15
// speedup vs baseline: 1.1575x; 1.0262x over previous
#include <cuda_runtime.h>
#include <cuda_bf16.h>
#include <math.h>
#include <cstdint>

#define NN 1500
#define NE 1200
#define NB 96
#define NSEG 1536
#define K2 3072            // storage K width: 2 segments [h | l]
#define NTOT 3072          // output rows, n8-group interleaved: even group=mu, odd=s2
#define MM 96              // batch rows (6 x m16)
#define NT 128             // N-tile per CTA
#define NTILES 24          // NTOT/NT
#define KSP 12             // split-K over the real axis
#define KR 128             // real-k per CTA = NSEG/KSP
#define KCH 32             // real-k per smem chunk
#define CH 4               // KR/KCH
#define NSTEPS 60
#define UTOT (NB * NN)

// padded smem row: 32 bf16 data + 8 pad = 40 bf16 = 80 bytes (ldmatrix conflict-free)
#define ROWB 80
#define T_A (MM * ROWB)              // 7680
#define T_B (NT * ROWB)              // 10240
#define OFF_AH 0
#define OFF_AL T_A
#define OFF_BH (2 * T_A)
#define OFF_BL (2 * T_A + T_B)
#define BUFSZ (2 * T_A + 2 * T_B)    // 35840
#define SMEM_TOTAL (3 * BUFSZ)       // 107520 (triple buffer)

typedef unsigned int u32;
typedef unsigned long long u64;

// ---------------- static device buffers ----------------
__device__ __align__(16) __nv_bfloat16 d_A[(size_t)MM * K2];       // [b][ah|al]
__device__ __align__(16) __nv_bfloat16 d_B[(size_t)NTOT * K2];     // [r][h|l] 18.9MB
__device__ __align__(16) float d_part[(size_t)KSP * NB * NTOT];    // 14.2MB
__device__ __align__(16) float d_rate[NB * NN];
__device__ __align__(16) float d_mean[NB * NN];

__constant__ float c_contr[8] = {0.0f, 0.0432773f, 0.103411f, 0.186966f,
                                 0.303066f, 0.464386f, 0.68854f, 1.0f};

// ---------------- PTX helpers (base ISA only) ----------------
__device__ __forceinline__ u32 smem_u32(const void* p) {
    u32 a;
    asm("{ .reg .u64 t; cvta.to.shared.u64 t, %1; cvt.u32.u64 %0, t; }" : "=r"(a) : "l"(p));
    return a;
}
__device__ __forceinline__ void ldsm4(u32& r0, u32& r1, u32& r2, u32& r3, u32 addr) {
    asm volatile("ldmatrix.sync.aligned.m8n8.x4.shared.b16 {%0,%1,%2,%3}, [%4];"
                 : "=r"(r0), "=r"(r1), "=r"(r2), "=r"(r3) : "r"(addr));
}
__device__ __forceinline__ void cpasync16(u32 saddr, const void* gaddr) {
    asm volatile("cp.async.cg.shared.global [%0], [%1], 16;" :: "r"(saddr), "l"(gaddr));
}
__device__ __forceinline__ void mma16816(float* c, u32 a0, u32 a1, u32 a2, u32 a3,
                                         u32 b0, u32 b1) {
    asm volatile("mma.sync.aligned.m16n8k16.row.col.f32.bf16.bf16.f32 "
                 "{%0,%1,%2,%3}, {%4,%5,%6,%7}, {%8,%9}, {%0,%1,%2,%3};"
                 : "+f"(c[0]), "+f"(c[1]), "+f"(c[2]), "+f"(c[3])
                 : "r"(a0), "r"(a1), "r"(a2), "r"(a3), "r"(b0), "r"(b1));
}

// ---------------- math helpers (MUFU fast-math; rel err ~1e-6 << 1e-3 budget) ----
__device__ __forceinline__ float prefv(int n) {
    const float se = 179.99f / 1200.0f;
    const float si = 179.99f / 300.0f;
    return (n < NE) ? (float)n * se : (float)(n - NE) * si;
}
__device__ __forceinline__ float f_ricci(float x) {
    float z = x / (1.0f + x);
    float t = -z;
    float p = 0.14805913578876898f;
    p = p * t + 0.64290613877355551f;
    p = p * t + 1.0616084849547165f;
    p = p * t + 0.93524391761244940f;
    p = p * t + 0.62718906618071668f;
    p = p * t + 0.32171431660633076f;
    p = p * t + 0.32056016125642045f;
    p = p * t + 0.77373949685442023f;
    p = p * t + 0.22757881388024176f;
    p = p * t + 0.0f;
    return __logf(2.0f * x + 1.0f) + p;
}
__device__ __forceinline__ float g_ricci(float x) {
    float z = x / (2.0f + x);
    float num = z * (3.5441754117462949f + z * (-7.0529131065835378f + z * (-56.532378057580381f
              + z * (279.56761105465944f + z * (-520.37554849441472f + z * (456.58245777026514f
              + z * (-155.73340457809226f)))))));
    float den = 1.0f + z * (-4.1357968834226053f + z * (-7.2984226138266743f + z * (98.656602235468327f
              + z * (-334.20436223415163f + z * (601.08633903294185f + z * (-599.58577549598340f
              + z * (277.18420330693891f + z * (-16.445022798669722f))))))));
    return num / den;
}
__device__ __forceinline__ float phi_f(float mu, float sig, float tau_ref) {
    const float tau = 0.01f;
    float xp = mu / sig;
    float xm = (mu - 20.0f) / sig;
    float r0;
    if (xm > 0.0f) {
        r0 = 1.0f / (f_ricci(xp) - f_ricci(xm));
    } else if (xp > 0.0f) {
        r0 = 1.0f / (f_ricci(xp) + __expf(xm * xm) * g_ricci(-xm));
    } else {
        r0 = __expf(-xm * xm - __logf(g_ricci(-xm) - __expf(xp * xp - xm * xm) * g_ricci(-xp)));
    }
    r0 = fmaxf(r0, 1e-30f);
    return 1.0f / (tau_ref + tau / r0);
}

// ---------------- setup kernels ----------------
// Row mapping (n8-group interleave): neuron i ->
//   mu row = (i/8)*16 + (i%8)   (even 8-row group)
//   s2 row = mu row + 8         (odd 8-row group)
// mu rows: segments [wh | wl]; s2 rows: [w2h | w2l]
// A segments [ah | al].  mu uses 3 pairings (ah*wh + ah*wl + al*wh);
// s2 uses 2 pairings (ah*w2h + ah*w2l) -- al*w2h dropped (positive sums, no cancellation).
__global__ void k_weightsB(const float* __restrict__ hyp, const float* __restrict__ rnd) {
    int tid = blockIdx.x * blockDim.x + threadIdx.x;
    if (tid >= NSEG * NSEG) return;
    int i = tid / NSEG;          // output neuron
    int j = tid - i * NSEG;      // input neuron (K)
    float w = 0.0f;
    if (i < NN && j < NN) {
        int conn = (i >= NE ? 1 : 0) + 2 * (j >= NE ? 1 : 0);
        float J = hyp[conn], P = hyp[4 + conn], Wp = hyp[8 + conn];
        const float cd = 3.14159265358979323846f / 180.0f;
        float diff = fabsf(prefv(i) - prefv(j));
        float wden = 4.0f * (cd * Wp) * (cd * Wp);
        float z = __expf((__cosf(2.0f * cd * diff) - 1.0f) / wden);
        float x = 32.0f * (P * z - rnd[(size_t)i * NN + j]);
        w = J / (1.0f + __expf(-x));
    }
    float w2 = w * w;
    __nv_bfloat16 wh = __float2bfloat16(w);
    __nv_bfloat16 wl = __float2bfloat16(w - __bfloat162float(wh));
    __nv_bfloat16 vh = __float2bfloat16(w2);
    __nv_bfloat16 vl = __float2bfloat16(w2 - __bfloat162float(vh));
    int mur = (i >> 3) * 16 + (i & 7);
    size_t r1 = (size_t)mur * K2;
    size_t r2 = (size_t)(mur + 8) * K2;
    d_B[r1 + j] = wh; d_B[r1 + NSEG + j] = wl;
    d_B[r2 + j] = vh; d_B[r2 + NSEG + j] = vl;
}

__global__ void k_mean() {
    int tid = blockIdx.x * blockDim.x + threadIdx.x;
    if (tid >= NB * NN) return;
    int b = tid / NN;
    int n = tid - b * NN;
    int c = b / 12;
    int o = b - c * 12;
    const float cd = 3.14159265358979323846f / 180.0f;
    float dth = (float)o * 15.0f - prefv(n);
    const float wden = 4.0f * (cd * 30.0f) * (cd * 30.0f);
    float cg = __expf((__cosf(2.0f * cd * dth) - 1.0f) / wden);
    d_mean[tid] = c_contr[c] * 20.0f * cg;
}

__global__ void k_zeroA() {
    int tid = blockIdx.x * blockDim.x + threadIdx.x;
    if (tid < MM * K2) d_A[tid] = __float2bfloat16(0.0f);
}

// ---------------- bf16 mma.sync GEMM step ----------------
// grid (24 n-tiles, 12 split-K), 256 threads.
// n8-group interleave: within each warp's 32-wide n-tile and each jp, the ldsm4
// b-frag pair is (j0 = mu group, j1 = s2 group); mu gets 3 pairings, s2 gets 2.
// Uniform 5 MMAs per (mt, jp) on every warp -- perfectly balanced.
// Triple-buffered cp.async pipeline (distance 2, one barrier/chunk, validated R10).
__global__ __launch_bounds__(256, 2) void k_mma() {
    extern __shared__ char sm[];
    u32 sb = smem_u32(sm);
    const int tid = threadIdx.x, wid = tid >> 5, lane = tid & 31;
    const int n0 = blockIdx.x * NT;
    const int z = blockIdx.y;
    const int kbase = z * KR;

    const char* Agc = (const char*)d_A;
    const char* Bgc = (const char*)d_B;

    float acc[3][4][4];
#pragma unroll
    for (int mt = 0; mt < 3; mt++)
#pragma unroll
        for (int j = 0; j < 4; j++)
#pragma unroll
            for (int q = 0; q < 4; q++) acc[mt][j][q] = 0.0f;

    const int m_w = (wid & 1) * 48;
    const int n_off = (wid >> 1) * 32;              // multiple of 32 -> j0 group is even (mu)
    const int aRow = m_w + ((lane >> 3) & 1) * 8 + (lane & 7);
    const u32 aOff = (u32)(aRow * ROWB + ((lane >> 4) & 1) * 16);
    const int bRow = n_off + ((lane >> 4) & 1) * 8 + (lane & 7);
    const u32 bOff = (u32)(bRow * ROWB + ((lane >> 3) & 1) * 16);

    auto load_chunk = [&](int c, u32 buf) {
        int kg = kbase + c * KCH;
#pragma unroll
        for (int idx = tid; idx < MM * 4; idx += 256) {
            int row = idx >> 2, q = idx & 3;
            u32 so = (u32)(row * ROWB + q * 16);
            size_t go = ((size_t)row * K2 + kg + q * 8) * 2;
            cpasync16(buf + OFF_AH + so, Agc + go);
            cpasync16(buf + OFF_AL + so, Agc + go + (size_t)NSEG * 2);
        }
#pragma unroll
        for (int idx = tid; idx < NT * 4; idx += 256) {
            int row = idx >> 2, q = idx & 3;
            u32 so = (u32)(row * ROWB + q * 16);
            size_t go = ((size_t)(n0 + row) * K2 + kg + q * 8) * 2;
            cpasync16(buf + OFF_BH + so, Bgc + go);
            cpasync16(buf + OFF_BL + so, Bgc + go + (size_t)NSEG * 2);
        }
        asm volatile("cp.async.commit_group;" ::: "memory");
    };

    load_chunk(0, sb);
    load_chunk(1, sb + BUFSZ);

#pragma unroll
    for (int c = 0; c < CH; c++) {
        if (c < CH - 1) {
            asm volatile("cp.async.wait_group 1;" ::: "memory");
        } else {
            asm volatile("cp.async.wait_group 0;" ::: "memory");
        }
        __syncthreads();
        if (c + 2 < CH) load_chunk(c + 2, sb + ((c + 2) % 3) * (u32)BUFSZ);

        u32 buf = sb + (c % 3) * (u32)BUFSZ;
#pragma unroll
        for (int ks = 0; ks < 2; ks++) {
            u32 kcol = (u32)(ks * 32);
            u32 ah[3][4], al[3][4];
#pragma unroll
            for (int mt = 0; mt < 3; mt++) {
                u32 off = aOff + (u32)(mt * 16 * ROWB) + kcol;
                ldsm4(ah[mt][0], ah[mt][1], ah[mt][2], ah[mt][3], buf + OFF_AH + off);
                ldsm4(al[mt][0], al[mt][1], al[mt][2], al[mt][3], buf + OFF_AL + off);
            }
#pragma unroll
            for (int jp = 0; jp < 2; jp++) {
                u32 off = bOff + (u32)(jp * 16 * ROWB) + kcol;
                u32 h00, h01, h10, h11, l00, l01, l10, l11;
                ldsm4(h00, h01, h10, h11, buf + OFF_BH + off);   // j0(mu): k0,k8 ; j1(s2): k0,k8
                ldsm4(l00, l01, l10, l11, buf + OFF_BL + off);
#pragma unroll
                for (int mt = 0; mt < 3; mt++) {
                    // mu column (j = 2jp): 3 pairings
                    mma16816(acc[mt][2 * jp],     ah[mt][0], ah[mt][1], ah[mt][2], ah[mt][3], h00, h01);
                    mma16816(acc[mt][2 * jp],     ah[mt][0], ah[mt][1], ah[mt][2], ah[mt][3], l00, l01);
                    mma16816(acc[mt][2 * jp],     al[mt][0], al[mt][1], al[mt][2], al[mt][3], h00, h01);
                    // s2 column (j = 2jp+1): 2 pairings (al*vh dropped)
                    mma16816(acc[mt][2 * jp + 1], ah[mt][0], ah[mt][1], ah[mt][2], ah[mt][3], h10, h11);
                    mma16816(acc[mt][2 * jp + 1], ah[mt][0], ah[mt][1], ah[mt][2], ah[mt][3], l10, l11);
                }
            }
        }
    }

    const int grp = lane >> 2;
#pragma unroll
    for (int mt = 0; mt < 3; mt++) {
        int br0 = m_w + mt * 16 + grp;
        int br1 = br0 + 8;
#pragma unroll
        for (int j = 0; j < 4; j++) {
            int col = n0 + n_off + j * 8 + (lane & 3) * 2;
            *(float2*)(d_part + ((size_t)z * NB + br0) * NTOT + col) =
                make_float2(acc[mt][j][0], acc[mt][j][1]);
            *(float2*)(d_part + ((size_t)z * NB + br1) * NTOT + col) =
                make_float2(acc[mt][j][2], acc[mt][j][3]);
        }
    }
}

// ---------------- reduce + phi + Euler update + A split write ----------------
// Item (b, n): mu partial at col (n/8)*16 + n%8, s2 partial at +8 (both coalesced
// across threads at 32B-sector granularity).
__global__ void k_update(int first, int last, float* __restrict__ out) {
    int tid = blockIdx.x * blockDim.x + threadIdx.x;
    if (tid >= UTOT) return;
    int b = tid / NN;
    int n = tid - b * NN;

    float ms = 0.0f, ss = 0.0f, rold = 0.0f;
    if (!first) {
        rold = d_rate[tid];
        int mur = (n >> 3) * 16 + (n & 7);
        const float* pp = d_part + (size_t)b * NTOT + mur;
#pragma unroll
        for (int z = 0; z < KSP; z++) {
            ms += pp[(size_t)z * NB * NTOT];
            ss += pp[(size_t)z * NB * NTOT + 8];
        }
    }
    float mu  = 0.01f * ms + d_mean[tid];
    float sig = sqrtf(0.01f * ss + 25.0f);
    float tr = (n < NE) ? 0.005f : 0.001f;
    float aT = (n < NE) ? 0.1f : 0.2f;
    float ph = phi_f(mu, sig, tr);
    float rnew = rold + aT * (ph - rold);
    d_rate[tid] = rnew;

    __nv_bfloat16 ah = __float2bfloat16(rnew);
    __nv_bfloat16 al = __float2bfloat16(rnew - __bfloat162float(ah));
    size_t ar = (size_t)b * K2 + n;
    d_A[ar]        = ah;
    d_A[ar + NSEG] = al;

    if (last) out[(size_t)n * NB + b] = rnew;        // out[n][b] = rate[b][n]
}

// ---------------- launch ----------------
extern "C" void kernel_launch(void* const* d_in, const int* in_sizes, int n_in,
                              void* d_out, int out_size) {
    const float* hyp = (const float*)d_in[0];
    const float* rnd = (const float*)d_in[1];
    float* out = (float*)d_out;

    cudaFuncSetAttribute(k_mma, cudaFuncAttributeMaxDynamicSharedMemorySize, SMEM_TOTAL);

    k_weightsB<<<(NSEG * NSEG + 255) / 256, 256>>>(hyp, rnd);
    k_mean<<<(NB * NN + 255) / 256, 256>>>();
    k_zeroA<<<(MM * K2 + 255) / 256, 256>>>();

    const int UB = (UTOT + 255) / 256;
    k_update<<<UB, 256>>>(1, 0, out);                 // step 1: rate=0 -> mu=mean
    for (int s = 1; s < NSTEPS; s++) {
        k_mma<<<dim3(NTILES, KSP), 256, SMEM_TOTAL>>>();
        k_update<<<UB, 256>>>(0, s == NSTEPS - 1 ? 1 : 0, out);
    }
}

// round 16
// speedup vs baseline: 1.2254x; 1.0587x over previous
#include <cuda_runtime.h>
#include <cuda_bf16.h>
#include <math.h>
#include <cstdint>

#define NN 1500
#define NE 1200
#define NB 96
#define NSEG 1536
#define K2 3072            // storage K width: 2 segments [h | l]
#define NTOT 3072          // output rows, n8-group interleaved: even group=mu, odd=s2
#define MM 96              // batch rows (6 x m16)
#define NT 128             // N-tile per CTA
#define NTILES 24          // NTOT/NT
#define KSP 12             // split-K over the real axis
#define KR 128             // real-k per CTA = NSEG/KSP
#define KCH 32             // real-k per smem chunk
#define CH 4               // KR/KCH
#define NSTEPS 60
#define UTOT (NB * NN)

// padded smem row: 32 bf16 data + 8 pad = 40 bf16 = 80 bytes (ldmatrix conflict-free)
#define ROWB 80
#define T_A (MM * ROWB)              // 7680
#define T_B (NT * ROWB)              // 10240
#define OFF_AH 0
#define OFF_AL T_A
#define OFF_BH (2 * T_A)
#define OFF_BL (2 * T_A + T_B)
#define BUFSZ (2 * T_A + 2 * T_B)    // 35840
#define SMEM_TOTAL (3 * BUFSZ)       // 107520 (triple buffer)

typedef unsigned int u32;
typedef unsigned long long u64;

// ---------------- static device buffers ----------------
__device__ __align__(16) __nv_bfloat16 d_A[(size_t)MM * K2];       // [b][ah|al]
__device__ __align__(16) __nv_bfloat16 d_B[(size_t)NTOT * K2];     // [r][h|l] 18.9MB
__device__ __align__(16) float d_part[(size_t)KSP * NB * NTOT];    // 14.2MB
__device__ __align__(16) float d_rate[NB * NN];
__device__ __align__(16) float d_mean[NB * NN];

__constant__ float c_contr[8] = {0.0f, 0.0432773f, 0.103411f, 0.186966f,
                                 0.303066f, 0.464386f, 0.68854f, 1.0f};

// ---------------- PTX helpers (base ISA only) ----------------
__device__ __forceinline__ u32 smem_u32(const void* p) {
    u32 a;
    asm("{ .reg .u64 t; cvta.to.shared.u64 t, %1; cvt.u32.u64 %0, t; }" : "=r"(a) : "l"(p));
    return a;
}
__device__ __forceinline__ void ldsm4(u32& r0, u32& r1, u32& r2, u32& r3, u32 addr) {
    asm volatile("ldmatrix.sync.aligned.m8n8.x4.shared.b16 {%0,%1,%2,%3}, [%4];"
                 : "=r"(r0), "=r"(r1), "=r"(r2), "=r"(r3) : "r"(addr));
}
__device__ __forceinline__ void cpasync16(u32 saddr, const void* gaddr) {
    asm volatile("cp.async.cg.shared.global [%0], [%1], 16;" :: "r"(saddr), "l"(gaddr));
}
__device__ __forceinline__ void mma16816(float* c, u32 a0, u32 a1, u32 a2, u32 a3,
                                         u32 b0, u32 b1) {
    asm volatile("mma.sync.aligned.m16n8k16.row.col.f32.bf16.bf16.f32 "
                 "{%0,%1,%2,%3}, {%4,%5,%6,%7}, {%8,%9}, {%0,%1,%2,%3};"
                 : "+f"(c[0]), "+f"(c[1]), "+f"(c[2]), "+f"(c[3])
                 : "r"(a0), "r"(a1), "r"(a2), "r"(a3), "r"(b0), "r"(b1));
}

// ---------------- math helpers (MUFU fast-math; rel err ~1e-6 << 1e-3 budget) ----
__device__ __forceinline__ float prefv(int n) {
    const float se = 179.99f / 1200.0f;
    const float si = 179.99f / 300.0f;
    return (n < NE) ? (float)n * se : (float)(n - NE) * si;
}
__device__ __forceinline__ float f_ricci(float x) {
    float z = x / (1.0f + x);
    float t = -z;
    float p = 0.14805913578876898f;
    p = p * t + 0.64290613877355551f;
    p = p * t + 1.0616084849547165f;
    p = p * t + 0.93524391761244940f;
    p = p * t + 0.62718906618071668f;
    p = p * t + 0.32171431660633076f;
    p = p * t + 0.32056016125642045f;
    p = p * t + 0.77373949685442023f;
    p = p * t + 0.22757881388024176f;
    p = p * t + 0.0f;
    return __logf(2.0f * x + 1.0f) + p;
}
__device__ __forceinline__ float g_ricci(float x) {
    float z = x / (2.0f + x);
    float num = z * (3.5441754117462949f + z * (-7.0529131065835378f + z * (-56.532378057580381f
              + z * (279.56761105465944f + z * (-520.37554849441472f + z * (456.58245777026514f
              + z * (-155.73340457809226f)))))));
    float den = 1.0f + z * (-4.1357968834226053f + z * (-7.2984226138266743f + z * (98.656602235468327f
              + z * (-334.20436223415163f + z * (601.08633903294185f + z * (-599.58577549598340f
              + z * (277.18420330693891f + z * (-16.445022798669722f))))))));
    return num / den;
}
__device__ __forceinline__ float phi_f(float mu, float sig, float tau_ref) {
    const float tau = 0.01f;
    float xp = mu / sig;
    float xm = (mu - 20.0f) / sig;
    float r0;
    if (xm > 0.0f) {
        r0 = 1.0f / (f_ricci(xp) - f_ricci(xm));
    } else if (xp > 0.0f) {
        r0 = 1.0f / (f_ricci(xp) + __expf(xm * xm) * g_ricci(-xm));
    } else {
        r0 = __expf(-xm * xm - __logf(g_ricci(-xm) - __expf(xp * xp - xm * xm) * g_ricci(-xp)));
    }
    r0 = fmaxf(r0, 1e-30f);
    return 1.0f / (tau_ref + tau / r0);
}

// ---------------- setup kernels ----------------
// Row mapping (n8-group interleave): neuron i ->
//   mu row = (i/8)*16 + (i%8)   (even 8-row group)
//   s2 row = mu row + 8         (odd 8-row group)
// mu rows: segments [wh | wl]; s2 rows: [w2h | (w2l unused)]
// A segments [ah | al].
//   mu: 3 pairings (ah*wh + ah*wl + al*wh)   -- cancellation-sensitive, keep all
//   s2: 1 pairing  (ah*w2h)                  -- positive sums; dropped terms are
//       random-sign rel ~2^-9 per weight -> ~3e-5 on the 1536-term sum
__global__ void k_weightsB(const float* __restrict__ hyp, const float* __restrict__ rnd) {
    int tid = blockIdx.x * blockDim.x + threadIdx.x;
    if (tid >= NSEG * NSEG) return;
    int i = tid / NSEG;          // output neuron
    int j = tid - i * NSEG;      // input neuron (K)
    float w = 0.0f;
    if (i < NN && j < NN) {
        int conn = (i >= NE ? 1 : 0) + 2 * (j >= NE ? 1 : 0);
        float J = hyp[conn], P = hyp[4 + conn], Wp = hyp[8 + conn];
        const float cd = 3.14159265358979323846f / 180.0f;
        float diff = fabsf(prefv(i) - prefv(j));
        float wden = 4.0f * (cd * Wp) * (cd * Wp);
        float z = __expf((__cosf(2.0f * cd * diff) - 1.0f) / wden);
        float x = 32.0f * (P * z - rnd[(size_t)i * NN + j]);
        w = J / (1.0f + __expf(-x));
    }
    float w2 = w * w;
    __nv_bfloat16 wh = __float2bfloat16(w);
    __nv_bfloat16 wl = __float2bfloat16(w - __bfloat162float(wh));
    __nv_bfloat16 vh = __float2bfloat16(w2);
    int mur = (i >> 3) * 16 + (i & 7);
    size_t r1 = (size_t)mur * K2;
    size_t r2 = (size_t)(mur + 8) * K2;
    d_B[r1 + j] = wh; d_B[r1 + NSEG + j] = wl;
    d_B[r2 + j] = vh; d_B[r2 + NSEG + j] = __float2bfloat16(0.0f);  // never loaded
}

__global__ void k_mean() {
    int tid = blockIdx.x * blockDim.x + threadIdx.x;
    if (tid >= NB * NN) return;
    int b = tid / NN;
    int n = tid - b * NN;
    int c = b / 12;
    int o = b - c * 12;
    const float cd = 3.14159265358979323846f / 180.0f;
    float dth = (float)o * 15.0f - prefv(n);
    const float wden = 4.0f * (cd * 30.0f) * (cd * 30.0f);
    float cg = __expf((__cosf(2.0f * cd * dth) - 1.0f) / wden);
    d_mean[tid] = c_contr[c] * 20.0f * cg;
}

__global__ void k_zeroA() {
    int tid = blockIdx.x * blockDim.x + threadIdx.x;
    if (tid < MM * K2) d_A[tid] = __float2bfloat16(0.0f);
}

// ---------------- bf16 mma.sync GEMM step ----------------
// grid (24 n-tiles, 12 split-K), 256 threads.
// Per (mt, jp): mu column 3 MMAs + s2 column 1 MMA = 4 (uniform on every warp).
// B-l loads are skipped for s2 rows (odd n8 groups) -- their smem is never read
// (the spanning ldsm4 returns garbage into provably-unused registers).
// Triple-buffered cp.async pipeline (distance 2, one barrier/chunk, validated R10).
__global__ __launch_bounds__(256, 2) void k_mma() {
    extern __shared__ char sm[];
    u32 sb = smem_u32(sm);
    const int tid = threadIdx.x, wid = tid >> 5, lane = tid & 31;
    const int n0 = blockIdx.x * NT;
    const int z = blockIdx.y;
    const int kbase = z * KR;

    const char* Agc = (const char*)d_A;
    const char* Bgc = (const char*)d_B;

    float acc[3][4][4];
#pragma unroll
    for (int mt = 0; mt < 3; mt++)
#pragma unroll
        for (int j = 0; j < 4; j++)
#pragma unroll
            for (int q = 0; q < 4; q++) acc[mt][j][q] = 0.0f;

    const int m_w = (wid & 1) * 48;
    const int n_off = (wid >> 1) * 32;              // multiple of 32 -> j0 group is even (mu)
    const int aRow = m_w + ((lane >> 3) & 1) * 8 + (lane & 7);
    const u32 aOff = (u32)(aRow * ROWB + ((lane >> 4) & 1) * 16);
    const int bRow = n_off + ((lane >> 4) & 1) * 8 + (lane & 7);
    const u32 bOff = (u32)(bRow * ROWB + ((lane >> 3) & 1) * 16);

    auto load_chunk = [&](int c, u32 buf) {
        int kg = kbase + c * KCH;
#pragma unroll
        for (int idx = tid; idx < MM * 4; idx += 256) {
            int row = idx >> 2, q = idx & 3;
            u32 so = (u32)(row * ROWB + q * 16);
            size_t go = ((size_t)row * K2 + kg + q * 8) * 2;
            cpasync16(buf + OFF_AH + so, Agc + go);
            cpasync16(buf + OFF_AL + so, Agc + go + (size_t)NSEG * 2);
        }
#pragma unroll
        for (int idx = tid; idx < NT * 4; idx += 256) {
            int row = idx >> 2, q = idx & 3;
            u32 so = (u32)(row * ROWB + q * 16);
            size_t go = ((size_t)(n0 + row) * K2 + kg + q * 8) * 2;
            cpasync16(buf + OFF_BH + so, Bgc + go);
            if (((row >> 3) & 1) == 0)               // l-segment: mu rows only
                cpasync16(buf + OFF_BL + so, Bgc + go + (size_t)NSEG * 2);
        }
        asm volatile("cp.async.commit_group;" ::: "memory");
    };

    load_chunk(0, sb);
    load_chunk(1, sb + BUFSZ);

#pragma unroll
    for (int c = 0; c < CH; c++) {
        if (c < CH - 1) {
            asm volatile("cp.async.wait_group 1;" ::: "memory");
        } else {
            asm volatile("cp.async.wait_group 0;" ::: "memory");
        }
        __syncthreads();
        if (c + 2 < CH) load_chunk(c + 2, sb + ((c + 2) % 3) * (u32)BUFSZ);

        u32 buf = sb + (c % 3) * (u32)BUFSZ;
#pragma unroll
        for (int ks = 0; ks < 2; ks++) {
            u32 kcol = (u32)(ks * 32);
            u32 ah[3][4], al[3][4];
#pragma unroll
            for (int mt = 0; mt < 3; mt++) {
                u32 off = aOff + (u32)(mt * 16 * ROWB) + kcol;
                ldsm4(ah[mt][0], ah[mt][1], ah[mt][2], ah[mt][3], buf + OFF_AH + off);
                ldsm4(al[mt][0], al[mt][1], al[mt][2], al[mt][3], buf + OFF_AL + off);
            }
#pragma unroll
            for (int jp = 0; jp < 2; jp++) {
                u32 off = bOff + (u32)(jp * 16 * ROWB) + kcol;
                u32 h00, h01, h10, h11, l00, l01, l10, l11;
                ldsm4(h00, h01, h10, h11, buf + OFF_BH + off);   // j0(mu), j1(s2)
                ldsm4(l00, l01, l10, l11, buf + OFF_BL + off);   // l10,l11 garbage (unused)
#pragma unroll
                for (int mt = 0; mt < 3; mt++) {
                    // mu column (j = 2jp): 3 pairings
                    mma16816(acc[mt][2 * jp],     ah[mt][0], ah[mt][1], ah[mt][2], ah[mt][3], h00, h01);
                    mma16816(acc[mt][2 * jp],     ah[mt][0], ah[mt][1], ah[mt][2], ah[mt][3], l00, l01);
                    mma16816(acc[mt][2 * jp],     al[mt][0], al[mt][1], al[mt][2], al[mt][3], h00, h01);
                    // s2 column (j = 2jp+1): 1 pairing (high terms only)
                    mma16816(acc[mt][2 * jp + 1], ah[mt][0], ah[mt][1], ah[mt][2], ah[mt][3], h10, h11);
                }
            }
        }
    }

    const int grp = lane >> 2;
#pragma unroll
    for (int mt = 0; mt < 3; mt++) {
        int br0 = m_w + mt * 16 + grp;
        int br1 = br0 + 8;
#pragma unroll
        for (int j = 0; j < 4; j++) {
            int col = n0 + n_off + j * 8 + (lane & 3) * 2;
            *(float2*)(d_part + ((size_t)z * NB + br0) * NTOT + col) =
                make_float2(acc[mt][j][0], acc[mt][j][1]);
            *(float2*)(d_part + ((size_t)z * NB + br1) * NTOT + col) =
                make_float2(acc[mt][j][2], acc[mt][j][3]);
        }
    }
}

// ---------------- reduce + phi + Euler update + A split write ----------------
// Item (b, n): mu partial at col (n/8)*16 + n%8, s2 partial at +8.
__global__ void k_update(int first, int last, float* __restrict__ out) {
    int tid = blockIdx.x * blockDim.x + threadIdx.x;
    if (tid >= UTOT) return;
    int b = tid / NN;
    int n = tid - b * NN;

    float ms = 0.0f, ss = 0.0f, rold = 0.0f;
    if (!first) {
        rold = d_rate[tid];
        int mur = (n >> 3) * 16 + (n & 7);
        const float* pp = d_part + (size_t)b * NTOT + mur;
#pragma unroll
        for (int z = 0; z < KSP; z++) {
            ms += pp[(size_t)z * NB * NTOT];
            ss += pp[(size_t)z * NB * NTOT + 8];
        }
    }
    float mu  = 0.01f * ms + d_mean[tid];
    float sig = sqrtf(0.01f * ss + 25.0f);
    float tr = (n < NE) ? 0.005f : 0.001f;
    float aT = (n < NE) ? 0.1f : 0.2f;
    float ph = phi_f(mu, sig, tr);
    float rnew = rold + aT * (ph - rold);
    d_rate[tid] = rnew;

    __nv_bfloat16 ah = __float2bfloat16(rnew);
    __nv_bfloat16 al = __float2bfloat16(rnew - __bfloat162float(ah));
    size_t ar = (size_t)b * K2 + n;
    d_A[ar]        = ah;
    d_A[ar + NSEG] = al;

    if (last) out[(size_t)n * NB + b] = rnew;        // out[n][b] = rate[b][n]
}

// ---------------- launch ----------------
extern "C" void kernel_launch(void* const* d_in, const int* in_sizes, int n_in,
                              void* d_out, int out_size) {
    const float* hyp = (const float*)d_in[0];
    const float* rnd = (const float*)d_in[1];
    float* out = (float*)d_out;

    cudaFuncSetAttribute(k_mma, cudaFuncAttributeMaxDynamicSharedMemorySize, SMEM_TOTAL);

    k_weightsB<<<(NSEG * NSEG + 255) / 256, 256>>>(hyp, rnd);
    k_mean<<<(NB * NN + 255) / 256, 256>>>();
    k_zeroA<<<(MM * K2 + 255) / 256, 256>>>();

    const int UB = (UTOT + 255) / 256;
    k_update<<<UB, 256>>>(1, 0, out);                 // step 1: rate=0 -> mu=mean
    for (int s = 1; s < NSTEPS; s++) {
        k_mma<<<dim3(NTILES, KSP), 256, SMEM_TOTAL>>>();
        k_update<<<UB, 256>>>(0, s == NSTEPS - 1 ? 1 : 0, out);
    }
}

// round 17
// speedup vs baseline: 1.3157x; 1.0737x over previous
#include <cuda_runtime.h>
#include <cuda_bf16.h>
#include <math.h>
#include <cstdint>

#define NN 1500
#define NE 1200
#define NB 96
#define NSEG 1536
#define K2 3072            // storage K width: 2 segments [h | l]
#define NTOT 3072          // output rows, n8-group interleaved: even group=mu, odd=s2
#define MM 96              // batch rows (6 x m16)
#define NT 128             // N-tile per CTA
#define NTILES 24          // NTOT/NT
#define KSP 6              // split-K over the real axis (144 CTAs = 1/SM)
#define KR 256             // real-k per CTA = NSEG/KSP
#define KCH 32             // real-k per smem chunk
#define CH 8               // KR/KCH
#define NBUF 4             // pipeline buffers (prefetch distance 3)
#define NSTEPS 60
#define UTOT (NB * NN)

// padded smem row: 32 bf16 data + 8 pad = 40 bf16 = 80 bytes (ldmatrix conflict-free)
#define ROWB 80
#define T_A (MM * ROWB)              // 7680
#define T_B (NT * ROWB)              // 10240
#define OFF_AH 0
#define OFF_AL T_A
#define OFF_BH (2 * T_A)
#define OFF_BL (2 * T_A + T_B)
#define BUFSZ (2 * T_A + 2 * T_B)    // 35840
#define SMEM_TOTAL (NBUF * BUFSZ)    // 143360 (quad buffer)

typedef unsigned int u32;
typedef unsigned long long u64;

// ---------------- static device buffers ----------------
__device__ __align__(16) __nv_bfloat16 d_A[(size_t)MM * K2];       // [b][ah|al]
__device__ __align__(16) __nv_bfloat16 d_B[(size_t)NTOT * K2];     // [r][h|l] 18.9MB
__device__ __align__(16) float d_part[(size_t)KSP * NB * NTOT];    // 7.1MB
__device__ __align__(16) float d_rate[NB * NN];
__device__ __align__(16) float d_mean[NB * NN];

__constant__ float c_contr[8] = {0.0f, 0.0432773f, 0.103411f, 0.186966f,
                                 0.303066f, 0.464386f, 0.68854f, 1.0f};

// ---------------- PTX helpers (base ISA only) ----------------
__device__ __forceinline__ u32 smem_u32(const void* p) {
    u32 a;
    asm("{ .reg .u64 t; cvta.to.shared.u64 t, %1; cvt.u32.u64 %0, t; }" : "=r"(a) : "l"(p));
    return a;
}
__device__ __forceinline__ void ldsm4(u32& r0, u32& r1, u32& r2, u32& r3, u32 addr) {
    asm volatile("ldmatrix.sync.aligned.m8n8.x4.shared.b16 {%0,%1,%2,%3}, [%4];"
                 : "=r"(r0), "=r"(r1), "=r"(r2), "=r"(r3) : "r"(addr));
}
__device__ __forceinline__ void cpasync16(u32 saddr, const void* gaddr) {
    asm volatile("cp.async.cg.shared.global [%0], [%1], 16;" :: "r"(saddr), "l"(gaddr));
}
__device__ __forceinline__ void mma16816(float* c, u32 a0, u32 a1, u32 a2, u32 a3,
                                         u32 b0, u32 b1) {
    asm volatile("mma.sync.aligned.m16n8k16.row.col.f32.bf16.bf16.f32 "
                 "{%0,%1,%2,%3}, {%4,%5,%6,%7}, {%8,%9}, {%0,%1,%2,%3};"
                 : "+f"(c[0]), "+f"(c[1]), "+f"(c[2]), "+f"(c[3])
                 : "r"(a0), "r"(a1), "r"(a2), "r"(a3), "r"(b0), "r"(b1));
}

// ---------------- math helpers (MUFU fast-math; rel err ~1e-6 << 1e-3 budget) ----
__device__ __forceinline__ float prefv(int n) {
    const float se = 179.99f / 1200.0f;
    const float si = 179.99f / 300.0f;
    return (n < NE) ? (float)n * se : (float)(n - NE) * si;
}
__device__ __forceinline__ float f_ricci(float x) {
    float z = x / (1.0f + x);
    float t = -z;
    float p = 0.14805913578876898f;
    p = p * t + 0.64290613877355551f;
    p = p * t + 1.0616084849547165f;
    p = p * t + 0.93524391761244940f;
    p = p * t + 0.62718906618071668f;
    p = p * t + 0.32171431660633076f;
    p = p * t + 0.32056016125642045f;
    p = p * t + 0.77373949685442023f;
    p = p * t + 0.22757881388024176f;
    p = p * t + 0.0f;
    return __logf(2.0f * x + 1.0f) + p;
}
__device__ __forceinline__ float g_ricci(float x) {
    float z = x / (2.0f + x);
    float num = z * (3.5441754117462949f + z * (-7.0529131065835378f + z * (-56.532378057580381f
              + z * (279.56761105465944f + z * (-520.37554849441472f + z * (456.58245777026514f
              + z * (-155.73340457809226f)))))));
    float den = 1.0f + z * (-4.1357968834226053f + z * (-7.2984226138266743f + z * (98.656602235468327f
              + z * (-334.20436223415163f + z * (601.08633903294185f + z * (-599.58577549598340f
              + z * (277.18420330693891f + z * (-16.445022798669722f))))))));
    return num / den;
}
__device__ __forceinline__ float phi_f(float mu, float sig, float tau_ref) {
    const float tau = 0.01f;
    float xp = mu / sig;
    float xm = (mu - 20.0f) / sig;
    float r0;
    if (xm > 0.0f) {
        r0 = 1.0f / (f_ricci(xp) - f_ricci(xm));
    } else if (xp > 0.0f) {
        r0 = 1.0f / (f_ricci(xp) + __expf(xm * xm) * g_ricci(-xm));
    } else {
        r0 = __expf(-xm * xm - __logf(g_ricci(-xm) - __expf(xp * xp - xm * xm) * g_ricci(-xp)));
    }
    r0 = fmaxf(r0, 1e-30f);
    return 1.0f / (tau_ref + tau / r0);
}

// ---------------- setup kernels ----------------
// Row mapping (n8-group interleave): neuron i ->
//   mu row = (i/8)*16 + (i%8); s2 row = mu row + 8
// mu rows: [wh | wl]; s2 rows: [w2h | unused]
// mu: 3 pairings (ah*wh + ah*wl + al*wh); s2: 1 pairing (ah*w2h)
__global__ void k_weightsB(const float* __restrict__ hyp, const float* __restrict__ rnd) {
    int tid = blockIdx.x * blockDim.x + threadIdx.x;
    if (tid >= NSEG * NSEG) return;
    int i = tid / NSEG;          // output neuron
    int j = tid - i * NSEG;      // input neuron (K)
    float w = 0.0f;
    if (i < NN && j < NN) {
        int conn = (i >= NE ? 1 : 0) + 2 * (j >= NE ? 1 : 0);
        float J = hyp[conn], P = hyp[4 + conn], Wp = hyp[8 + conn];
        const float cd = 3.14159265358979323846f / 180.0f;
        float diff = fabsf(prefv(i) - prefv(j));
        float wden = 4.0f * (cd * Wp) * (cd * Wp);
        float z = __expf((__cosf(2.0f * cd * diff) - 1.0f) / wden);
        float x = 32.0f * (P * z - rnd[(size_t)i * NN + j]);
        w = J / (1.0f + __expf(-x));
    }
    float w2 = w * w;
    __nv_bfloat16 wh = __float2bfloat16(w);
    __nv_bfloat16 wl = __float2bfloat16(w - __bfloat162float(wh));
    __nv_bfloat16 vh = __float2bfloat16(w2);
    int mur = (i >> 3) * 16 + (i & 7);
    size_t r1 = (size_t)mur * K2;
    size_t r2 = (size_t)(mur + 8) * K2;
    d_B[r1 + j] = wh; d_B[r1 + NSEG + j] = wl;
    d_B[r2 + j] = vh; d_B[r2 + NSEG + j] = __float2bfloat16(0.0f);  // never loaded
}

__global__ void k_mean() {
    int tid = blockIdx.x * blockDim.x + threadIdx.x;
    if (tid >= NB * NN) return;
    int b = tid / NN;
    int n = tid - b * NN;
    int c = b / 12;
    int o = b - c * 12;
    const float cd = 3.14159265358979323846f / 180.0f;
    float dth = (float)o * 15.0f - prefv(n);
    const float wden = 4.0f * (cd * 30.0f) * (cd * 30.0f);
    float cg = __expf((__cosf(2.0f * cd * dth) - 1.0f) / wden);
    d_mean[tid] = c_contr[c] * 20.0f * cg;
}

__global__ void k_zeroA() {
    int tid = blockIdx.x * blockDim.x + threadIdx.x;
    if (tid < MM * K2) d_A[tid] = __float2bfloat16(0.0f);
}

// ---------------- bf16 mma.sync GEMM step ----------------
// grid (24 n-tiles, 6 split-K) = 144 CTAs (1/SM), 256 threads.
// Quad-buffered cp.async pipeline, prefetch distance 3, one barrier per chunk:
//   iter c: wait(chunk c) -> barrier -> prefetch c+3 into buf (c+3)%4 -> compute c.
// Per (mt, jp): mu column 3 MMAs + s2 column 1 MMA (uniform per warp).
__global__ __launch_bounds__(256, 1) void k_mma() {
    extern __shared__ char sm[];
    u32 sb = smem_u32(sm);
    const int tid = threadIdx.x, wid = tid >> 5, lane = tid & 31;
    const int n0 = blockIdx.x * NT;
    const int z = blockIdx.y;
    const int kbase = z * KR;

    const char* Agc = (const char*)d_A;
    const char* Bgc = (const char*)d_B;

    float acc[3][4][4];
#pragma unroll
    for (int mt = 0; mt < 3; mt++)
#pragma unroll
        for (int j = 0; j < 4; j++)
#pragma unroll
            for (int q = 0; q < 4; q++) acc[mt][j][q] = 0.0f;

    const int m_w = (wid & 1) * 48;
    const int n_off = (wid >> 1) * 32;              // multiple of 32 -> j0 group is mu
    const int aRow = m_w + ((lane >> 3) & 1) * 8 + (lane & 7);
    const u32 aOff = (u32)(aRow * ROWB + ((lane >> 4) & 1) * 16);
    const int bRow = n_off + ((lane >> 4) & 1) * 8 + (lane & 7);
    const u32 bOff = (u32)(bRow * ROWB + ((lane >> 3) & 1) * 16);

    auto load_chunk = [&](int c, u32 buf) {
        int kg = kbase + c * KCH;
#pragma unroll
        for (int idx = tid; idx < MM * 4; idx += 256) {
            int row = idx >> 2, q = idx & 3;
            u32 so = (u32)(row * ROWB + q * 16);
            size_t go = ((size_t)row * K2 + kg + q * 8) * 2;
            cpasync16(buf + OFF_AH + so, Agc + go);
            cpasync16(buf + OFF_AL + so, Agc + go + (size_t)NSEG * 2);
        }
#pragma unroll
        for (int idx = tid; idx < NT * 4; idx += 256) {
            int row = idx >> 2, q = idx & 3;
            u32 so = (u32)(row * ROWB + q * 16);
            size_t go = ((size_t)(n0 + row) * K2 + kg + q * 8) * 2;
            cpasync16(buf + OFF_BH + so, Bgc + go);
            if (((row >> 3) & 1) == 0)               // l-segment: mu rows only
                cpasync16(buf + OFF_BL + so, Bgc + go + (size_t)NSEG * 2);
        }
        asm volatile("cp.async.commit_group;" ::: "memory");
    };

    // prologue: chunks 0..2 into buffers 0..2
    load_chunk(0, sb);
    load_chunk(1, sb + BUFSZ);
    load_chunk(2, sb + 2 * BUFSZ);

#pragma unroll
    for (int c = 0; c < CH; c++) {
        // 1) chunk c's group complete (min(2, CH-1-c) younger groups may remain)
        if (c < CH - 2) {
            asm volatile("cp.async.wait_group 2;" ::: "memory");
        } else if (c == CH - 2) {
            asm volatile("cp.async.wait_group 1;" ::: "memory");
        } else {
            asm volatile("cp.async.wait_group 0;" ::: "memory");
        }
        // 2) visible to all; all warps done reading buffer (c-1)%NBUF
        __syncthreads();
        // 3) refill buffer (c+3)%NBUF == (c-1)%NBUF
        if (c + 3 < CH) load_chunk(c + 3, sb + ((c + 3) % NBUF) * (u32)BUFSZ);

        // 4) compute chunk c
        u32 buf = sb + (c % NBUF) * (u32)BUFSZ;
#pragma unroll
        for (int ks = 0; ks < 2; ks++) {
            u32 kcol = (u32)(ks * 32);
            u32 ah[3][4], al[3][4];
#pragma unroll
            for (int mt = 0; mt < 3; mt++) {
                u32 off = aOff + (u32)(mt * 16 * ROWB) + kcol;
                ldsm4(ah[mt][0], ah[mt][1], ah[mt][2], ah[mt][3], buf + OFF_AH + off);
                ldsm4(al[mt][0], al[mt][1], al[mt][2], al[mt][3], buf + OFF_AL + off);
            }
#pragma unroll
            for (int jp = 0; jp < 2; jp++) {
                u32 off = bOff + (u32)(jp * 16 * ROWB) + kcol;
                u32 h00, h01, h10, h11, l00, l01, l10, l11;
                ldsm4(h00, h01, h10, h11, buf + OFF_BH + off);   // j0(mu), j1(s2)
                ldsm4(l00, l01, l10, l11, buf + OFF_BL + off);   // l10,l11 unused
#pragma unroll
                for (int mt = 0; mt < 3; mt++) {
                    mma16816(acc[mt][2 * jp],     ah[mt][0], ah[mt][1], ah[mt][2], ah[mt][3], h00, h01);
                    mma16816(acc[mt][2 * jp],     ah[mt][0], ah[mt][1], ah[mt][2], ah[mt][3], l00, l01);
                    mma16816(acc[mt][2 * jp],     al[mt][0], al[mt][1], al[mt][2], al[mt][3], h00, h01);
                    mma16816(acc[mt][2 * jp + 1], ah[mt][0], ah[mt][1], ah[mt][2], ah[mt][3], h10, h11);
                }
            }
        }
    }

    const int grp = lane >> 2;
#pragma unroll
    for (int mt = 0; mt < 3; mt++) {
        int br0 = m_w + mt * 16 + grp;
        int br1 = br0 + 8;
#pragma unroll
        for (int j = 0; j < 4; j++) {
            int col = n0 + n_off + j * 8 + (lane & 3) * 2;
            *(float2*)(d_part + ((size_t)z * NB + br0) * NTOT + col) =
                make_float2(acc[mt][j][0], acc[mt][j][1]);
            *(float2*)(d_part + ((size_t)z * NB + br1) * NTOT + col) =
                make_float2(acc[mt][j][2], acc[mt][j][3]);
        }
    }
}

// ---------------- reduce + phi + Euler update + A split write ----------------
// Item (b, n): mu partial at col (n/8)*16 + n%8, s2 partial at +8.
__global__ void k_update(int first, int last, float* __restrict__ out) {
    int tid = blockIdx.x * blockDim.x + threadIdx.x;
    if (tid >= UTOT) return;
    int b = tid / NN;
    int n = tid - b * NN;

    float ms = 0.0f, ss = 0.0f, rold = 0.0f;
    if (!first) {
        rold = d_rate[tid];
        int mur = (n >> 3) * 16 + (n & 7);
        const float* pp = d_part + (size_t)b * NTOT + mur;
#pragma unroll
        for (int z = 0; z < KSP; z++) {
            ms += pp[(size_t)z * NB * NTOT];
            ss += pp[(size_t)z * NB * NTOT + 8];
        }
    }
    float mu  = 0.01f * ms + d_mean[tid];
    float sig = sqrtf(0.01f * ss + 25.0f);
    float tr = (n < NE) ? 0.005f : 0.001f;
    float aT = (n < NE) ? 0.1f : 0.2f;
    float ph = phi_f(mu, sig, tr);
    float rnew = rold + aT * (ph - rold);
    d_rate[tid] = rnew;

    __nv_bfloat16 ah = __float2bfloat16(rnew);
    __nv_bfloat16 al = __float2bfloat16(rnew - __bfloat162float(ah));
    size_t ar = (size_t)b * K2 + n;
    d_A[ar]        = ah;
    d_A[ar + NSEG] = al;

    if (last) out[(size_t)n * NB + b] = rnew;        // out[n][b] = rate[b][n]
}

// ---------------- launch ----------------
extern "C" void kernel_launch(void* const* d_in, const int* in_sizes, int n_in,
                              void* d_out, int out_size) {
    const float* hyp = (const float*)d_in[0];
    const float* rnd = (const float*)d_in[1];
    float* out = (float*)d_out;

    cudaFuncSetAttribute(k_mma, cudaFuncAttributeMaxDynamicSharedMemorySize, SMEM_TOTAL);

    k_weightsB<<<(NSEG * NSEG + 255) / 256, 256>>>(hyp, rnd);
    k_mean<<<(NB * NN + 255) / 256, 256>>>();
    k_zeroA<<<(MM * K2 + 255) / 256, 256>>>();

    const int UB = (UTOT + 255) / 256;
    k_update<<<UB, 256>>>(1, 0, out);                 // step 1: rate=0 -> mu=mean
    for (int s = 1; s < NSTEPS; s++) {
        k_mma<<<dim3(NTILES, KSP), 256, SMEM_TOTAL>>>();
        k_update<<<UB, 256>>>(0, s == NSTEPS - 1 ? 1 : 0, out);
    }
}